// round 14
// baseline (speedup 1.0000x reference)
#include <cuda_runtime.h>
#include <cstdint>
#include <math.h>

#define S_T   12
#define NN    16384
#define EE    262144          // 2^18
#define D     128
#define BB    64
#define TT    3072            // S*N/B
#define ROWS  (S_T*NN)        // 196608
#define NEDGE (S_T*EE)        // 3,145,728
#define NRB   1536            // row-blocks of 128 rows (= 2 timesteps each)
#define TSPLIT 1216           // LSTM split point (timesteps)
#define ITEM_OFS (TSPLIT*2)   // first gatesx item handled inside combo
#define NITEMS_TOT (NRB*4)    // 6144

// ---- scratch (static device allocations; no runtime alloc allowed) ----
__device__ __align__(16) float g_support[(size_t)ROWS * D];
__device__ __align__(16) float g_acc[(size_t)ROWS * D];
__device__ __align__(16) float g_gx[(size_t)ROWS * 512];
__device__ int g_deg[ROWS];
__device__ int g_off[ROWS];
__device__ int g_cur[ROWS];
__device__ int g_bsum[256];
__device__ __align__(16) int2 g_epack[NEDGE];
__device__ int g_ticket;
__device__ __align__(16) float g_hstate[BB * 128];
__device__ __align__(16) float g_cstate[BB * 128];

// ---- packed f32x2 helpers ----
typedef unsigned long long u64;
__device__ __forceinline__ void ffma2(u64& d, u64 a, u64 b, u64 c) {
    asm("fma.rn.f32x2 %0, %1, %2, %3;" : "=l"(d) : "l"(a), "l"(b), "l"(c));
}
__device__ __forceinline__ u64 bcast2(float x) {
    u64 r;
    asm("mov.b64 %0, {%1, %1};" : "=l"(r) : "f"(x));
    return r;
}
__device__ __forceinline__ float2 unpack2(u64 v) {
    float2 r;
    asm("mov.b64 {%0, %1}, %2;" : "=f"(r.x), "=f"(r.y) : "l"(v));
    return r;
}
__device__ __forceinline__ float fsigm(float x) {
    return __fdividef(1.f, 1.f + __expf(-x));
}
__device__ __forceinline__ float ftanh(float x) {
    return __fdividef(2.f, 1.f + __expf(-2.f * x)) - 1.f;
}

// ============================================================
// init: zero degree counters + ticket
// ============================================================
__global__ void init_kernel() {
    int gid = blockIdx.x * 1024 + threadIdx.x;
    g_deg[gid] = 0;
    if (gid == 0) g_ticket = 0;
}

// ============================================================
// support tile (device fn): 128x128 of support = xs @ W
// ============================================================
__device__ __forceinline__ void support_tile(int blk, const float* __restrict__ X,
                                             const float* __restrict__ W) {
    extern __shared__ float sm[];
    float* As = sm;
    float* Bs = sm + 64 * 132;

    int tid = threadIdx.x;
    int tx = tid & 15, ty = tid >> 4;
    size_t rowbase = (size_t)blk * 128;

    u64 accp[8][4];
#pragma unroll
    for (int i = 0; i < 8; ++i)
#pragma unroll
        for (int jj = 0; jj < 4; ++jj) accp[i][jj] = 0ull;

    for (int k0 = 0; k0 < 128; k0 += 64) {
        __syncthreads();
        for (int idx = tid; idx < 128 * 64; idx += 256) {
            int r = idx >> 6, k = idx & 63;
            As[k * 132 + r] = X[(rowbase + r) * 128 + k0 + k];
        }
        for (int idx = tid; idx < 64 * 128; idx += 256) {
            int k = idx >> 7, c = idx & 127;
            Bs[k * 132 + c] = W[(size_t)(k0 + k) * 128 + c];
        }
        __syncthreads();
#pragma unroll
        for (int k = 0; k < 64; ++k) {
            ulonglong2 b0 = *(const ulonglong2*)&Bs[k * 132 + tx * 4];
            ulonglong2 b1 = *(const ulonglong2*)&Bs[k * 132 + 64 + tx * 4];
            float4 a0 = *(const float4*)&As[k * 132 + ty * 4];
            float4 a1 = *(const float4*)&As[k * 132 + 64 + ty * 4];
            float af[8] = {a0.x,a0.y,a0.z,a0.w,a1.x,a1.y,a1.z,a1.w};
#pragma unroll
            for (int i = 0; i < 8; ++i) {
                u64 ap = bcast2(af[i]);
                ffma2(accp[i][0], ap, b0.x, accp[i][0]);
                ffma2(accp[i][1], ap, b0.y, accp[i][1]);
                ffma2(accp[i][2], ap, b1.x, accp[i][2]);
                ffma2(accp[i][3], ap, b1.y, accp[i][3]);
            }
        }
    }
#pragma unroll
    for (int i = 0; i < 8; ++i) {
        int r = (i < 4) ? (ty * 4 + i) : (64 + ty * 4 + i - 4);
        float* crow = g_support + (rowbase + r) * 128;
        float2 v0 = unpack2(accp[i][0]), v1 = unpack2(accp[i][1]);
        float2 v2 = unpack2(accp[i][2]), v3 = unpack2(accp[i][3]);
        *(float4*)&crow[tx * 4]      = make_float4(v0.x, v0.y, v1.x, v1.y);
        *(float4*)&crow[64 + tx * 4] = make_float4(v2.x, v2.y, v3.x, v3.y);
    }
}

// ============================================================
// K_a: support tiles (blocks 0..1535) || fat histogram (rest)
// hist blocks: 256 thr x 8 edges = 2048 edges/block, 1536 blocks.
// Latency-tolerant at the 3 CTA/SM occupancy GEMM_SMEM allows.
// ============================================================
__global__ void __launch_bounds__(256)
ka_kernel(const float* __restrict__ X, const float* __restrict__ W,
          const int* __restrict__ adj_idx) {
    if (blockIdx.x < 1536) { support_tile(blockIdx.x, X, W); return; }
    int base = (blockIdx.x - 1536) * 2048 + threadIdx.x;
#pragma unroll
    for (int i = 0; i < 8; ++i) {
        int gid = base + i * 256;                 // 0..NEDGE-1
        int s = gid >> 18, e = gid & (EE - 1);
        int dst = adj_idx[(size_t)s * 2 * EE + e];
        atomicAdd(&g_deg[s * NN + dst], 1);
    }
}

// ============================================================
// CSR scans + fill (scan1: warp-shuffle, 2 barriers)
// ============================================================
__global__ void scan1_kernel() {                 // 192 blocks x 1024
    __shared__ int wsum[32];
    int tid = threadIdx.x, lane = tid & 31, warp = tid >> 5;
    int gid = blockIdx.x * 1024 + tid;
    int x = g_deg[gid];
    int v = x;
#pragma unroll
    for (int d = 1; d < 32; d <<= 1) {
        int t = __shfl_up_sync(0xffffffffu, v, d);
        if (lane >= d) v += t;
    }
    if (lane == 31) wsum[warp] = v;
    __syncthreads();
    if (warp == 0) {
        int w = wsum[lane];
#pragma unroll
        for (int d = 1; d < 32; d <<= 1) {
            int t = __shfl_up_sync(0xffffffffu, w, d);
            if (lane >= d) w += t;
        }
        wsum[lane] = w;
    }
    __syncthreads();
    int base = warp ? wsum[warp - 1] : 0;
    g_off[gid] = base + v - x;                   // exclusive
    if (tid == 1023) g_bsum[blockIdx.x] = base + v;
}

__global__ void scan2_kernel() {                 // 1 block x 256
    __shared__ int tmp[256];
    int tid = threadIdx.x;
    int x = (tid < 192) ? g_bsum[tid] : 0;
    tmp[tid] = x;
    __syncthreads();
#pragma unroll
    for (int d = 1; d < 256; d <<= 1) {
        int t = (tid >= d) ? tmp[tid - d] : 0;
        __syncthreads();
        tmp[tid] += t;
        __syncthreads();
    }
    if (tid < 192) g_bsum[tid] = tmp[tid] - x;   // exclusive
}

__global__ void scan3_kernel() {                 // 192 blocks x 1024
    int gid = blockIdx.x * 1024 + threadIdx.x;
    int v = g_off[gid] + g_bsum[blockIdx.x];
    g_off[gid] = v;
    g_cur[gid] = v;
}

__global__ void fill_kernel(const int* __restrict__ adj_idx,
                            const float* __restrict__ adj_val) {
    int gid = blockIdx.x * 1024 + threadIdx.x;
    int s = gid >> 18, e = gid & (EE - 1);
    const int* ib = adj_idx + (size_t)s * 2 * EE;
    int dst = ib[e];
    int src = ib[EE + e];
    float v  = adj_val[(size_t)s * EE + e];
    int pos = atomicAdd(&g_cur[s * NN + dst], 1);
    g_epack[pos] = make_int2(src, __float_as_int(v));
}

// ============================================================
// gather: acc[row] = sum_e val[e] * support[src[e]]
// ============================================================
__global__ void __launch_bounds__(256)
gather_kernel() {
    int wid  = blockIdx.x * 8 + (threadIdx.x >> 5);
    int lane = threadIdx.x & 31;
    int s = wid >> 14;

    int start = g_off[wid];
    int cnt   = g_deg[wid];

    const int2*  epk  = g_epack + start;
    const float* supp = g_support + (size_t)s * NN * D + lane * 4;

    float ax = 0.f, ay = 0.f, az = 0.f, aw = 0.f;
    int i = 0;
    for (; i + 4 <= cnt; i += 4) {
        int2 p0 = __ldg(&epk[i + 0]);
        int2 p1 = __ldg(&epk[i + 1]);
        int2 p2 = __ldg(&epk[i + 2]);
        int2 p3 = __ldg(&epk[i + 3]);
        float4 m0 = *(const float4*)(supp + (size_t)p0.x * D);
        float4 m1 = *(const float4*)(supp + (size_t)p1.x * D);
        float4 m2 = *(const float4*)(supp + (size_t)p2.x * D);
        float4 m3 = *(const float4*)(supp + (size_t)p3.x * D);
        float v0 = __int_as_float(p0.y), v1 = __int_as_float(p1.y);
        float v2 = __int_as_float(p2.y), v3 = __int_as_float(p3.y);
        ax += v0 * m0.x; ay += v0 * m0.y; az += v0 * m0.z; aw += v0 * m0.w;
        ax += v1 * m1.x; ay += v1 * m1.y; az += v1 * m1.z; aw += v1 * m1.w;
        ax += v2 * m2.x; ay += v2 * m2.y; az += v2 * m2.z; aw += v2 * m2.w;
        ax += v3 * m3.x; ay += v3 * m3.y; az += v3 * m3.z; aw += v3 * m3.w;
    }
    for (; i < cnt; ++i) {
        int2 p = __ldg(&epk[i]);
        float v = __int_as_float(p.y);
        float4 m = *(const float4*)(supp + (size_t)p.x * D);
        ax += v * m.x; ay += v * m.y; az += v * m.z; aw += v * m.w;
    }
    *(float4*)(g_acc + (size_t)wid * D + lane * 4) = make_float4(ax, ay, az, aw);
}

// ============================================================
// gatesx part A: rb < TSPLIT/2
// ============================================================
__global__ void __launch_bounds__(256)
gatesxA_kernel(const float* __restrict__ wih, const float* __restrict__ gcn_bias) {
    extern __shared__ float sm[];
    float* As = sm;
    float* Bs = sm + 64 * 132;

    int tid = threadIdx.x;
    int tx = tid & 15, ty = tid >> 4;
    size_t rowbase = (size_t)blockIdx.x * 128;
    int cb = blockIdx.y;

    u64 accp[8][4];
#pragma unroll
    for (int i = 0; i < 8; ++i)
#pragma unroll
        for (int jj = 0; jj < 4; ++jj) accp[i][jj] = 0ull;

    for (int k0 = 0; k0 < 128; k0 += 64) {
        __syncthreads();
        for (int idx = tid; idx < 128 * 64; idx += 256) {
            int r = idx >> 6, k = idx & 63;
            float x = g_acc[(rowbase + r) * 128 + k0 + k] + __ldg(&gcn_bias[k0 + k]);
            As[k * 132 + r] = fmaxf(x, 0.f);
        }
        for (int idx = tid; idx < 128 * 64; idx += 256) {
            int c = idx >> 6, k = idx & 63;
            Bs[k * 132 + c] = wih[((size_t)(cb * 128 + c)) * 128 + k0 + k];
        }
        __syncthreads();
#pragma unroll
        for (int k = 0; k < 64; ++k) {
            ulonglong2 b0 = *(const ulonglong2*)&Bs[k * 132 + tx * 4];
            ulonglong2 b1 = *(const ulonglong2*)&Bs[k * 132 + 64 + tx * 4];
            float4 a0 = *(const float4*)&As[k * 132 + ty * 4];
            float4 a1 = *(const float4*)&As[k * 132 + 64 + ty * 4];
            float af[8] = {a0.x,a0.y,a0.z,a0.w,a1.x,a1.y,a1.z,a1.w};
#pragma unroll
            for (int i = 0; i < 8; ++i) {
                u64 ap = bcast2(af[i]);
                ffma2(accp[i][0], ap, b0.x, accp[i][0]);
                ffma2(accp[i][1], ap, b0.y, accp[i][1]);
                ffma2(accp[i][2], ap, b1.x, accp[i][2]);
                ffma2(accp[i][3], ap, b1.y, accp[i][3]);
            }
        }
    }
#pragma unroll
    for (int i = 0; i < 8; ++i) {
        int r = (i < 4) ? (ty * 4 + i) : (64 + ty * 4 + i - 4);
        float* crow = g_gx + (rowbase + r) * 512 + cb * 128;
        float2 v0 = unpack2(accp[i][0]), v1 = unpack2(accp[i][1]);
        float2 v2 = unpack2(accp[i][2]), v3 = unpack2(accp[i][3]);
        *(float4*)&crow[tx * 4]      = make_float4(v0.x, v0.y, v1.x, v1.y);
        *(float4*)&crow[64 + tx * 4] = make_float4(v2.x, v2.y, v3.x, v3.y);
    }
}

// ============================================================
// LSTM chain: one CTA per batch lane, 512 threads.
// Pair p=t>>1, K-half pos=t&1; partials exchanged via SHFL.BFLY
// with lane-neighbor; each thread finalizes ONE output and
// applies its own nonlinearity. gx prefetched 2 steps ahead.
// ============================================================
__device__ __forceinline__ void lstm_chain(
    int b, int t0, int t1,
    const float* __restrict__ hin, const float* __restrict__ cin,
    const float* __restrict__ whh, const float* __restrict__ bih,
    const float* __restrict__ bhh, float* __restrict__ out)
{
    extern __shared__ float sm[];
    float* sWs = sm;                  // [1024 slices][16] stride 20, slice = o*2+pos
    float* sH  = sm + 1024 * 20;      // [136]: half h at pos*68
    float* sC  = sH + 136;            // [128]
    float* sG  = sC + 128;            // [516]: sG[o + (o>=256)*4]

    int t = threadIdx.x;              // 0..511
    int p = t >> 1, pos = t & 1;
    int oa = p, ob = p + 256;
    int kb = pos * 64;
    int ofin = pos ? ob : oa;

    for (int idx = t; idx < 1024 * 16; idx += 512) {
        int slice = idx >> 4, kk = idx & 15;
        int o = slice >> 1, ps = slice & 1;
        sWs[slice * 20 + kk] = whh[(size_t)o * 128 + ps * 64 + kk];
    }
    u64 wra[24], wrb[24];
#pragma unroll
    for (int m = 0; m < 24; ++m) {
        wra[m] = *(const u64*)&whh[(size_t)oa * 128 + kb + 16 + 2 * m];
        wrb[m] = *(const u64*)&whh[(size_t)ob * 128 + kb + 16 + 2 * m];
    }

    if (t < 128) {
        sH[(t >> 6) * 68 + (t & 63)] = hin[b * 128 + t];
        sC[t] = cin[b * 128 + t];
    }
    float bias = bih[ofin] + bhh[ofin];
    int gate = ofin >> 7;
    float nsc = (gate == 2) ? 2.f : 1.f;      // tanh(x) = 2*sigm(2x) - 1
    float nof = (gate == 2) ? -1.f : 0.f;
    const float* gxp = g_gx + (size_t)b * 512 + ofin;
    float gxc = gxp[(size_t)t0 * 32768];
    float gx1 = (t0 + 1 < t1) ? gxp[(size_t)(t0 + 1) * 32768] : 0.f;
    __syncthreads();

    const float* wap = &sWs[(size_t)(oa * 2 + pos) * 20];
    const float* wbp = &sWs[(size_t)(ob * 2 + pos) * 20];
    const float* hp  = &sH[pos * 68];
    int sgi = ofin + ((ofin >> 8) << 2);

    for (int tt = t0; tt < t1; ++tt) {
        float gx2 = (tt + 2 < t1) ? gxp[(size_t)(tt + 2) * 32768] : 0.f;

        u64 a0 = 0ull, a1 = 0ull, b0 = 0ull, b1 = 0ull;
#pragma unroll
        for (int kk = 0; kk < 16; kk += 4) {
            ulonglong2 hv = *(const ulonglong2*)&hp[kk];
            ulonglong2 wa = *(const ulonglong2*)&wap[kk];
            ulonglong2 wb = *(const ulonglong2*)&wbp[kk];
            ffma2(a0, hv.x, wa.x, a0);  ffma2(a1, hv.y, wa.y, a1);
            ffma2(b0, hv.x, wb.x, b0);  ffma2(b1, hv.y, wb.y, b1);
        }
#pragma unroll
        for (int kk = 0; kk < 48; kk += 4) {
            ulonglong2 hv = *(const ulonglong2*)&hp[16 + kk];
            ffma2(a0, hv.x, wra[kk / 2], a0);  ffma2(a1, hv.y, wra[kk / 2 + 1], a1);
            ffma2(b0, hv.x, wrb[kk / 2], b0);  ffma2(b1, hv.y, wrb[kk / 2 + 1], b1);
        }
        float2 qa0 = unpack2(a0), qa1 = unpack2(a1);
        float2 qb0 = unpack2(b0), qb1 = unpack2(b1);
        float pa = (qa0.x + qa0.y) + (qa1.x + qa1.y);
        float pb = (qb0.x + qb0.y) + (qb1.x + qb1.y);
        float xa = pa + __shfl_xor_sync(0xffffffffu, pa, 1);
        float xb = pb + __shfl_xor_sync(0xffffffffu, pb, 1);
        float pre = (pos ? xb : xa) + gxc + bias;
        sG[sgi] = nsc * fsigm(nsc * pre) + nof;        // sigma or tanh
        __syncthreads();

        if (t < 128) {
            float i_ = sG[t],        f_ = sG[128 + t];
            float g_ = sG[260 + t],  o_ = sG[388 + t];
            float c = f_ * sC[t] + i_ * g_;
            sC[t] = c;
            float h = o_ * ftanh(c);
            sH[(t >> 6) * 68 + (t & 63)] = h;
            out[((size_t)tt * 64 + b) * 128 + t] = h;
        }
        __syncthreads();
        gxc = gx1; gx1 = gx2;
    }

    if (t < 128) {
        g_hstate[b * 128 + t] = sH[(t >> 6) * 68 + (t & 63)];
        g_cstate[b * 128 + t] = sC[t];
    }
}

// ============================================================
// COMBO kernel: 148 CTAs x 512 threads, NO cross-CTA comms.
//  CTA 0..63   : LSTM for t in [0, TSPLIT)
//  CTA 64..147 : gates_x producer for items [ITEM_OFS, NITEMS_TOT)
// ============================================================
__global__ void __launch_bounds__(512, 1)
combo_kernel(const float* __restrict__ wih,  const float* __restrict__ gb,
             const float* __restrict__ whh,
             const float* __restrict__ bih,  const float* __restrict__ bhh,
             const float* __restrict__ h0,   const float* __restrict__ c0,
             float* __restrict__ out) {
    if (blockIdx.x < 64) {
        lstm_chain(blockIdx.x, 0, TSPLIT, h0, c0, whh, bih, bhh, out);
        return;
    }

    // ---------- producer: gates_x for items [ITEM_OFS, NITEMS_TOT) ----------
    extern __shared__ float sm[];
    float* As = sm;
    float* Bs = sm + 64 * 132;
    __shared__ int sItem;
    int tid = threadIdx.x;
    int tx = tid & 15, ty = tid >> 4;

    for (;;) {
        if (tid == 0) sItem = ITEM_OFS + atomicAdd(&g_ticket, 1);
        __syncthreads();
        int item = sItem;
        if (item >= NITEMS_TOT) break;
        int rb = item >> 2, cb = item & 3;
        size_t rowbase = (size_t)rb * 128;

        u64 accp[4][4];
#pragma unroll
        for (int i = 0; i < 4; ++i)
#pragma unroll
            for (int jj = 0; jj < 4; ++jj) accp[i][jj] = 0ull;

        for (int k0 = 0; k0 < 128; k0 += 64) {
            __syncthreads();
            for (int idx = tid; idx < 128 * 64; idx += 512) {
                int r = idx >> 6, k = idx & 63;
                float x = g_acc[(rowbase + r) * 128 + k0 + k] + __ldg(&gb[k0 + k]);
                As[k * 132 + r] = fmaxf(x, 0.f);
            }
            for (int idx = tid; idx < 128 * 64; idx += 512) {
                int c = idx >> 6, k = idx & 63;
                Bs[k * 132 + c] = wih[((size_t)(cb * 128 + c)) * 128 + k0 + k];
            }
            __syncthreads();
#pragma unroll
            for (int k = 0; k < 64; ++k) {
                ulonglong2 b0 = *(const ulonglong2*)&Bs[k * 132 + tx * 4];
                ulonglong2 b1 = *(const ulonglong2*)&Bs[k * 132 + 64 + tx * 4];
                float4 a = *(const float4*)&As[k * 132 + ty * 4];
                float af[4] = {a.x, a.y, a.z, a.w};
#pragma unroll
                for (int i = 0; i < 4; ++i) {
                    u64 ap = bcast2(af[i]);
                    ffma2(accp[i][0], ap, b0.x, accp[i][0]);
                    ffma2(accp[i][1], ap, b0.y, accp[i][1]);
                    ffma2(accp[i][2], ap, b1.x, accp[i][2]);
                    ffma2(accp[i][3], ap, b1.y, accp[i][3]);
                }
            }
        }
#pragma unroll
        for (int i = 0; i < 4; ++i) {
            float* crow = g_gx + (rowbase + ty * 4 + i) * 512 + cb * 128;
            float2 v0 = unpack2(accp[i][0]), v1 = unpack2(accp[i][1]);
            float2 v2 = unpack2(accp[i][2]), v3 = unpack2(accp[i][3]);
            *(float4*)&crow[tx * 4]      = make_float4(v0.x, v0.y, v1.x, v1.y);
            *(float4*)&crow[64 + tx * 4] = make_float4(v2.x, v2.y, v3.x, v3.y);
        }
        // consumers of these gx rows run in a LATER kernel launch
    }
}

// ============================================================
// LSTM part B: t in [TSPLIT, TT), state from device globals
// ============================================================
__global__ void __launch_bounds__(512, 1)
lstm2_kernel(const float* __restrict__ whh,
             const float* __restrict__ bih, const float* __restrict__ bhh,
             float* __restrict__ out) {
    lstm_chain(blockIdx.x, TSPLIT, TT, g_hstate, g_cstate, whh, bih, bhh, out);
}

// ============================================================
// launch
// ============================================================
extern "C" void kernel_launch(void* const* d_in, const int* in_sizes, int n_in,
                              void* d_out, int out_size) {
    const int*   adj_idx = (const int*)  d_in[0];
    const float* adj_val = (const float*)d_in[1];
    const float* xs      = (const float*)d_in[2];
    const float* gw      = (const float*)d_in[3];
    const float* gb      = (const float*)d_in[4];
    const float* wih     = (const float*)d_in[5];
    const float* whh     = (const float*)d_in[6];
    const float* bih     = (const float*)d_in[7];
    const float* bhh     = (const float*)d_in[8];
    const float* h0      = (const float*)d_in[9];
    const float* c0      = (const float*)d_in[10];
    float* out = (float*)d_out;

    (void)in_sizes; (void)n_in; (void)out_size;

    const int GEMM_SMEM = 2 * 64 * 132 * 4;                       // 67584
    const int LSTM_SMEM = (1024 * 20 + 136 + 128 + 516) * 4;      // 85040

    static bool attr_done = false;
    if (!attr_done) {
        cudaFuncSetAttribute(ka_kernel,      cudaFuncAttributeMaxDynamicSharedMemorySize, GEMM_SMEM);
        cudaFuncSetAttribute(gatesxA_kernel, cudaFuncAttributeMaxDynamicSharedMemorySize, GEMM_SMEM);
        cudaFuncSetAttribute(combo_kernel,   cudaFuncAttributeMaxDynamicSharedMemorySize, LSTM_SMEM);
        cudaFuncSetAttribute(lstm2_kernel,   cudaFuncAttributeMaxDynamicSharedMemorySize, LSTM_SMEM);
        attr_done = true;
    }

    // init
    init_kernel<<<192, 1024>>>();

    // support tiles (1536) || fat histogram (1536)
    ka_kernel<<<3072, 256, GEMM_SMEM>>>(xs, gw, adj_idx);

    // scans + fill
    scan1_kernel<<<192, 1024>>>();
    scan2_kernel<<<1, 256>>>();
    scan3_kernel<<<192, 1024>>>();
    fill_kernel<<<NEDGE / 1024, 1024>>>(adj_idx, adj_val);

    // gather
    gather_kernel<<<ROWS / 8, 256>>>();

    // gates_x for t < TSPLIT (rb < TSPLIT/2)
    gatesxA_kernel<<<dim3(TSPLIT / 2, 4), 256, GEMM_SMEM>>>(wih, gb);

    // overlap: LSTM[0,TSPLIT) on 64 CTAs || gates_x rb>=TSPLIT/2 on 84 CTAs
    combo_kernel<<<148, 512, LSTM_SMEM>>>(wih, gb, whh, bih, bhh, h0, c0, out);

    // LSTM [TSPLIT, TT)
    lstm2_kernel<<<64, 512, LSTM_SMEM>>>(whh, bih, bhh, out);
}

// round 15
// speedup vs baseline: 1.1978x; 1.1978x over previous
#include <cuda_runtime.h>
#include <cstdint>
#include <math.h>

#define S_T   12
#define NN    16384
#define EE    262144          // 2^18
#define D     128
#define BB    64
#define TT    3072            // S*N/B
#define ROWS  (S_T*NN)        // 196608
#define NEDGE (S_T*EE)        // 3,145,728
#define NRB   1536            // row-blocks of 128 rows (= 2 timesteps each)
#define TSPLIT 1216           // LSTM split point (timesteps)
#define ITEM_OFS (TSPLIT*2)   // first gatesx item handled inside combo
#define NITEMS_TOT (NRB*4)    // 6144

// ---- scratch (static device allocations; no runtime alloc allowed) ----
__device__ __align__(16) float g_support[(size_t)ROWS * D];
__device__ __align__(16) float g_acc[(size_t)ROWS * D];
__device__ __align__(16) float g_gx[(size_t)ROWS * 512];
__device__ int g_deg[ROWS];
__device__ int g_off[ROWS];
__device__ int g_cur[ROWS];
__device__ int g_bsum[256];
__device__ __align__(16) int2 g_epack[NEDGE];
__device__ int g_ticket;
__device__ __align__(16) float g_hstate[BB * 128];
__device__ __align__(16) float g_cstate[BB * 128];

// ---- packed f32x2 helpers ----
typedef unsigned long long u64;
__device__ __forceinline__ void ffma2(u64& d, u64 a, u64 b, u64 c) {
    asm("fma.rn.f32x2 %0, %1, %2, %3;" : "=l"(d) : "l"(a), "l"(b), "l"(c));
}
__device__ __forceinline__ u64 bcast2(float x) {
    u64 r;
    asm("mov.b64 %0, {%1, %1};" : "=l"(r) : "f"(x));
    return r;
}
__device__ __forceinline__ float2 unpack2(u64 v) {
    float2 r;
    asm("mov.b64 {%0, %1}, %2;" : "=f"(r.x), "=f"(r.y) : "l"(v));
    return r;
}
__device__ __forceinline__ float fsigm(float x) {
    return __fdividef(1.f, 1.f + __expf(-x));
}
__device__ __forceinline__ float ftanh(float x) {
    return __fdividef(2.f, 1.f + __expf(-2.f * x)) - 1.f;
}

// ============================================================
// init: zero degree counters + ticket
// ============================================================
__global__ void init_kernel() {
    int gid = blockIdx.x * 1024 + threadIdx.x;
    g_deg[gid] = 0;
    if (gid == 0) g_ticket = 0;
}

// ============================================================
// CSR pipeline: histogram -> scan -> fill (packs src+val)
// ============================================================
__global__ void hist_kernel(const int* __restrict__ adj_idx) {
    int gid = blockIdx.x * 1024 + threadIdx.x;
    int s = gid >> 18, e = gid & (EE - 1);
    int dst = adj_idx[(size_t)s * 2 * EE + e];
    atomicAdd(&g_deg[s * NN + dst], 1);
}

// scan1: warp-shuffle Hillis-Steele, 2 barriers total
__global__ void scan1_kernel() {                 // 192 blocks x 1024
    __shared__ int wsum[32];
    int tid = threadIdx.x, lane = tid & 31, warp = tid >> 5;
    int gid = blockIdx.x * 1024 + tid;
    int x = g_deg[gid];
    int v = x;
#pragma unroll
    for (int d = 1; d < 32; d <<= 1) {
        int t = __shfl_up_sync(0xffffffffu, v, d);
        if (lane >= d) v += t;
    }
    if (lane == 31) wsum[warp] = v;
    __syncthreads();
    if (warp == 0) {
        int w = wsum[lane];
#pragma unroll
        for (int d = 1; d < 32; d <<= 1) {
            int t = __shfl_up_sync(0xffffffffu, w, d);
            if (lane >= d) w += t;
        }
        wsum[lane] = w;
    }
    __syncthreads();
    int base = warp ? wsum[warp - 1] : 0;
    g_off[gid] = base + v - x;                   // exclusive
    if (tid == 1023) g_bsum[blockIdx.x] = base + v;
}

__global__ void scan2_kernel() {                 // 1 block x 256
    __shared__ int tmp[256];
    int tid = threadIdx.x;
    int x = (tid < 192) ? g_bsum[tid] : 0;
    tmp[tid] = x;
    __syncthreads();
#pragma unroll
    for (int d = 1; d < 256; d <<= 1) {
        int t = (tid >= d) ? tmp[tid - d] : 0;
        __syncthreads();
        tmp[tid] += t;
        __syncthreads();
    }
    if (tid < 192) g_bsum[tid] = tmp[tid] - x;   // exclusive
}

__global__ void scan3_kernel() {                 // 192 blocks x 1024
    int gid = blockIdx.x * 1024 + threadIdx.x;
    int v = g_off[gid] + g_bsum[blockIdx.x];
    g_off[gid] = v;
    g_cur[gid] = v;
}

__global__ void fill_kernel(const int* __restrict__ adj_idx,
                            const float* __restrict__ adj_val) {
    int gid = blockIdx.x * 1024 + threadIdx.x;
    int s = gid >> 18, e = gid & (EE - 1);
    const int* ib = adj_idx + (size_t)s * 2 * EE;
    int dst = ib[e];
    int src = ib[EE + e];
    float v  = adj_val[(size_t)s * EE + e];
    int pos = atomicAdd(&g_cur[s * NN + dst], 1);
    g_epack[pos] = make_int2(src, __float_as_int(v));
}

// ============================================================
// gather: acc[row] = sum_e val[e] * support[src[e]]
// ============================================================
__global__ void __launch_bounds__(256)
gather_kernel() {
    int wid  = blockIdx.x * 8 + (threadIdx.x >> 5);
    int lane = threadIdx.x & 31;
    int s = wid >> 14;

    int start = g_off[wid];
    int cnt   = g_deg[wid];

    const int2*  epk  = g_epack + start;
    const float* supp = g_support + (size_t)s * NN * D + lane * 4;

    float ax = 0.f, ay = 0.f, az = 0.f, aw = 0.f;
    int i = 0;
    for (; i + 4 <= cnt; i += 4) {
        int2 p0 = __ldg(&epk[i + 0]);
        int2 p1 = __ldg(&epk[i + 1]);
        int2 p2 = __ldg(&epk[i + 2]);
        int2 p3 = __ldg(&epk[i + 3]);
        float4 m0 = *(const float4*)(supp + (size_t)p0.x * D);
        float4 m1 = *(const float4*)(supp + (size_t)p1.x * D);
        float4 m2 = *(const float4*)(supp + (size_t)p2.x * D);
        float4 m3 = *(const float4*)(supp + (size_t)p3.x * D);
        float v0 = __int_as_float(p0.y), v1 = __int_as_float(p1.y);
        float v2 = __int_as_float(p2.y), v3 = __int_as_float(p3.y);
        ax += v0 * m0.x; ay += v0 * m0.y; az += v0 * m0.z; aw += v0 * m0.w;
        ax += v1 * m1.x; ay += v1 * m1.y; az += v1 * m1.z; aw += v1 * m1.w;
        ax += v2 * m2.x; ay += v2 * m2.y; az += v2 * m2.z; aw += v2 * m2.w;
        ax += v3 * m3.x; ay += v3 * m3.y; az += v3 * m3.z; aw += v3 * m3.w;
    }
    for (; i < cnt; ++i) {
        int2 p = __ldg(&epk[i]);
        float v = __int_as_float(p.y);
        float4 m = *(const float4*)(supp + (size_t)p.x * D);
        ax += v * m.x; ay += v * m.y; az += v * m.z; aw += v * m.w;
    }
    *(float4*)(g_acc + (size_t)wid * D + lane * 4) = make_float4(ax, ay, az, aw);
}

// ============================================================
// K1: support = xs @ gcn_weight (256 threads, 8x8 reg tile)
// ============================================================
__global__ void __launch_bounds__(256)
support_kernel(const float* __restrict__ X, const float* __restrict__ W) {
    extern __shared__ float sm[];
    float* As = sm;
    float* Bs = sm + 64 * 132;

    int tid = threadIdx.x;
    int tx = tid & 15, ty = tid >> 4;
    size_t rowbase = (size_t)blockIdx.x * 128;

    u64 accp[8][4];
#pragma unroll
    for (int i = 0; i < 8; ++i)
#pragma unroll
        for (int jj = 0; jj < 4; ++jj) accp[i][jj] = 0ull;

    for (int k0 = 0; k0 < 128; k0 += 64) {
        __syncthreads();
        for (int idx = tid; idx < 128 * 64; idx += 256) {
            int r = idx >> 6, k = idx & 63;
            As[k * 132 + r] = X[(rowbase + r) * 128 + k0 + k];
        }
        for (int idx = tid; idx < 64 * 128; idx += 256) {
            int k = idx >> 7, c = idx & 127;
            Bs[k * 132 + c] = W[(size_t)(k0 + k) * 128 + c];
        }
        __syncthreads();
#pragma unroll
        for (int k = 0; k < 64; ++k) {
            ulonglong2 b0 = *(const ulonglong2*)&Bs[k * 132 + tx * 4];
            ulonglong2 b1 = *(const ulonglong2*)&Bs[k * 132 + 64 + tx * 4];
            float4 a0 = *(const float4*)&As[k * 132 + ty * 4];
            float4 a1 = *(const float4*)&As[k * 132 + 64 + ty * 4];
            float af[8] = {a0.x,a0.y,a0.z,a0.w,a1.x,a1.y,a1.z,a1.w};
#pragma unroll
            for (int i = 0; i < 8; ++i) {
                u64 ap = bcast2(af[i]);
                ffma2(accp[i][0], ap, b0.x, accp[i][0]);
                ffma2(accp[i][1], ap, b0.y, accp[i][1]);
                ffma2(accp[i][2], ap, b1.x, accp[i][2]);
                ffma2(accp[i][3], ap, b1.y, accp[i][3]);
            }
        }
    }
#pragma unroll
    for (int i = 0; i < 8; ++i) {
        int r = (i < 4) ? (ty * 4 + i) : (64 + ty * 4 + i - 4);
        float* crow = g_support + (rowbase + r) * 128;
        float2 v0 = unpack2(accp[i][0]), v1 = unpack2(accp[i][1]);
        float2 v2 = unpack2(accp[i][2]), v3 = unpack2(accp[i][3]);
        *(float4*)&crow[tx * 4]      = make_float4(v0.x, v0.y, v1.x, v1.y);
        *(float4*)&crow[64 + tx * 4] = make_float4(v2.x, v2.y, v3.x, v3.y);
    }
}

// ============================================================
// gatesx part A: rb < TSPLIT/2
// ============================================================
__global__ void __launch_bounds__(256)
gatesxA_kernel(const float* __restrict__ wih, const float* __restrict__ gcn_bias) {
    extern __shared__ float sm[];
    float* As = sm;
    float* Bs = sm + 64 * 132;

    int tid = threadIdx.x;
    int tx = tid & 15, ty = tid >> 4;
    size_t rowbase = (size_t)blockIdx.x * 128;
    int cb = blockIdx.y;

    u64 accp[8][4];
#pragma unroll
    for (int i = 0; i < 8; ++i)
#pragma unroll
        for (int jj = 0; jj < 4; ++jj) accp[i][jj] = 0ull;

    for (int k0 = 0; k0 < 128; k0 += 64) {
        __syncthreads();
        for (int idx = tid; idx < 128 * 64; idx += 256) {
            int r = idx >> 6, k = idx & 63;
            float x = g_acc[(rowbase + r) * 128 + k0 + k] + __ldg(&gcn_bias[k0 + k]);
            As[k * 132 + r] = fmaxf(x, 0.f);
        }
        for (int idx = tid; idx < 128 * 64; idx += 256) {
            int c = idx >> 6, k = idx & 63;
            Bs[k * 132 + c] = wih[((size_t)(cb * 128 + c)) * 128 + k0 + k];
        }
        __syncthreads();
#pragma unroll
        for (int k = 0; k < 64; ++k) {
            ulonglong2 b0 = *(const ulonglong2*)&Bs[k * 132 + tx * 4];
            ulonglong2 b1 = *(const ulonglong2*)&Bs[k * 132 + 64 + tx * 4];
            float4 a0 = *(const float4*)&As[k * 132 + ty * 4];
            float4 a1 = *(const float4*)&As[k * 132 + 64 + ty * 4];
            float af[8] = {a0.x,a0.y,a0.z,a0.w,a1.x,a1.y,a1.z,a1.w};
#pragma unroll
            for (int i = 0; i < 8; ++i) {
                u64 ap = bcast2(af[i]);
                ffma2(accp[i][0], ap, b0.x, accp[i][0]);
                ffma2(accp[i][1], ap, b0.y, accp[i][1]);
                ffma2(accp[i][2], ap, b1.x, accp[i][2]);
                ffma2(accp[i][3], ap, b1.y, accp[i][3]);
            }
        }
    }
#pragma unroll
    for (int i = 0; i < 8; ++i) {
        int r = (i < 4) ? (ty * 4 + i) : (64 + ty * 4 + i - 4);
        float* crow = g_gx + (rowbase + r) * 512 + cb * 128;
        float2 v0 = unpack2(accp[i][0]), v1 = unpack2(accp[i][1]);
        float2 v2 = unpack2(accp[i][2]), v3 = unpack2(accp[i][3]);
        *(float4*)&crow[tx * 4]      = make_float4(v0.x, v0.y, v1.x, v1.y);
        *(float4*)&crow[64 + tx * 4] = make_float4(v2.x, v2.y, v3.x, v3.y);
    }
}

// ============================================================
// LSTM chain: one CTA per batch lane, 512 threads.
// Pair p=t>>1, K-half pos=t&1; partials exchanged via SHFL.BFLY
// with lane-neighbor; each thread finalizes ONE output and
// applies its own nonlinearity. gx prefetch distance 1.
// (R13 configuration — best known.)
// ============================================================
__device__ __forceinline__ void lstm_chain(
    int b, int t0, int t1,
    const float* __restrict__ hin, const float* __restrict__ cin,
    const float* __restrict__ whh, const float* __restrict__ bih,
    const float* __restrict__ bhh, float* __restrict__ out)
{
    extern __shared__ float sm[];
    float* sWs = sm;                  // [1024 slices][16] stride 20, slice = o*2+pos
    float* sH  = sm + 1024 * 20;      // [136]: half h at pos*68
    float* sC  = sH + 136;            // [128]
    float* sG  = sC + 128;            // [516]: sG[o + (o>=256)*4]

    int t = threadIdx.x;              // 0..511
    int p = t >> 1, pos = t & 1;
    int oa = p, ob = p + 256;
    int kb = pos * 64;
    int ofin = pos ? ob : oa;

    for (int idx = t; idx < 1024 * 16; idx += 512) {
        int slice = idx >> 4, kk = idx & 15;
        int o = slice >> 1, ps = slice & 1;
        sWs[slice * 20 + kk] = whh[(size_t)o * 128 + ps * 64 + kk];
    }
    u64 wra[24], wrb[24];
#pragma unroll
    for (int m = 0; m < 24; ++m) {
        wra[m] = *(const u64*)&whh[(size_t)oa * 128 + kb + 16 + 2 * m];
        wrb[m] = *(const u64*)&whh[(size_t)ob * 128 + kb + 16 + 2 * m];
    }

    if (t < 128) {
        sH[(t >> 6) * 68 + (t & 63)] = hin[b * 128 + t];
        sC[t] = cin[b * 128 + t];
    }
    float bias = bih[ofin] + bhh[ofin];
    int gate = ofin >> 7;
    float nsc = (gate == 2) ? 2.f : 1.f;      // tanh(x) = 2*sigm(2x) - 1
    float nof = (gate == 2) ? -1.f : 0.f;
    const float* gxp = g_gx + (size_t)b * 512 + ofin;
    float gxc = gxp[(size_t)t0 * 32768];
    __syncthreads();

    const float* wap = &sWs[(size_t)(oa * 2 + pos) * 20];
    const float* wbp = &sWs[(size_t)(ob * 2 + pos) * 20];
    const float* hp  = &sH[pos * 68];
    int sgi = ofin + ((ofin >> 8) << 2);

    for (int tt = t0; tt < t1; ++tt) {
        float gxn = (tt + 1 < t1) ? gxp[(size_t)(tt + 1) * 32768] : 0.f;

        u64 a0 = 0ull, a1 = 0ull, b0 = 0ull, b1 = 0ull;
#pragma unroll
        for (int kk = 0; kk < 16; kk += 4) {
            ulonglong2 hv = *(const ulonglong2*)&hp[kk];
            ulonglong2 wa = *(const ulonglong2*)&wap[kk];
            ulonglong2 wb = *(const ulonglong2*)&wbp[kk];
            ffma2(a0, hv.x, wa.x, a0);  ffma2(a1, hv.y, wa.y, a1);
            ffma2(b0, hv.x, wb.x, b0);  ffma2(b1, hv.y, wb.y, b1);
        }
#pragma unroll
        for (int kk = 0; kk < 48; kk += 4) {
            ulonglong2 hv = *(const ulonglong2*)&hp[16 + kk];
            ffma2(a0, hv.x, wra[kk / 2], a0);  ffma2(a1, hv.y, wra[kk / 2 + 1], a1);
            ffma2(b0, hv.x, wrb[kk / 2], b0);  ffma2(b1, hv.y, wrb[kk / 2 + 1], b1);
        }
        float2 qa0 = unpack2(a0), qa1 = unpack2(a1);
        float2 qb0 = unpack2(b0), qb1 = unpack2(b1);
        float pa = (qa0.x + qa0.y) + (qa1.x + qa1.y);
        float pb = (qb0.x + qb0.y) + (qb1.x + qb1.y);
        float xa = pa + __shfl_xor_sync(0xffffffffu, pa, 1);
        float xb = pb + __shfl_xor_sync(0xffffffffu, pb, 1);
        float pre = (pos ? xb : xa) + gxc + bias;
        sG[sgi] = nsc * fsigm(nsc * pre) + nof;        // sigma or tanh
        __syncthreads();

        if (t < 128) {
            float i_ = sG[t],        f_ = sG[128 + t];
            float g_ = sG[260 + t],  o_ = sG[388 + t];
            float c = f_ * sC[t] + i_ * g_;
            sC[t] = c;
            float h = o_ * ftanh(c);
            sH[(t >> 6) * 68 + (t & 63)] = h;
            out[((size_t)tt * 64 + b) * 128 + t] = h;
        }
        __syncthreads();
        gxc = gxn;
    }

    if (t < 128) {
        g_hstate[b * 128 + t] = sH[(t >> 6) * 68 + (t & 63)];
        g_cstate[b * 128 + t] = sC[t];
    }
}

// ============================================================
// COMBO kernel: 148 CTAs x 512 threads, NO cross-CTA comms.
//  CTA 0..63   : LSTM for t in [0, TSPLIT)
//  CTA 64..147 : gates_x producer for items [ITEM_OFS, NITEMS_TOT)
// ============================================================
__global__ void __launch_bounds__(512, 1)
combo_kernel(const float* __restrict__ wih,  const float* __restrict__ gb,
             const float* __restrict__ whh,
             const float* __restrict__ bih,  const float* __restrict__ bhh,
             const float* __restrict__ h0,   const float* __restrict__ c0,
             float* __restrict__ out) {
    if (blockIdx.x < 64) {
        lstm_chain(blockIdx.x, 0, TSPLIT, h0, c0, whh, bih, bhh, out);
        return;
    }

    // ---------- producer: gates_x for items [ITEM_OFS, NITEMS_TOT) ----------
    extern __shared__ float sm[];
    float* As = sm;
    float* Bs = sm + 64 * 132;
    __shared__ int sItem;
    int tid = threadIdx.x;
    int tx = tid & 15, ty = tid >> 4;

    for (;;) {
        if (tid == 0) sItem = ITEM_OFS + atomicAdd(&g_ticket, 1);
        __syncthreads();
        int item = sItem;
        if (item >= NITEMS_TOT) break;
        int rb = item >> 2, cb = item & 3;
        size_t rowbase = (size_t)rb * 128;

        u64 accp[4][4];
#pragma unroll
        for (int i = 0; i < 4; ++i)
#pragma unroll
            for (int jj = 0; jj < 4; ++jj) accp[i][jj] = 0ull;

        for (int k0 = 0; k0 < 128; k0 += 64) {
            __syncthreads();
            for (int idx = tid; idx < 128 * 64; idx += 512) {
                int r = idx >> 6, k = idx & 63;
                float x = g_acc[(rowbase + r) * 128 + k0 + k] + __ldg(&gb[k0 + k]);
                As[k * 132 + r] = fmaxf(x, 0.f);
            }
            for (int idx = tid; idx < 128 * 64; idx += 512) {
                int c = idx >> 6, k = idx & 63;
                Bs[k * 132 + c] = wih[((size_t)(cb * 128 + c)) * 128 + k0 + k];
            }
            __syncthreads();
#pragma unroll
            for (int k = 0; k < 64; ++k) {
                ulonglong2 b0 = *(const ulonglong2*)&Bs[k * 132 + tx * 4];
                ulonglong2 b1 = *(const ulonglong2*)&Bs[k * 132 + 64 + tx * 4];
                float4 a = *(const float4*)&As[k * 132 + ty * 4];
                float af[4] = {a.x, a.y, a.z, a.w};
#pragma unroll
                for (int i = 0; i < 4; ++i) {
                    u64 ap = bcast2(af[i]);
                    ffma2(accp[i][0], ap, b0.x, accp[i][0]);
                    ffma2(accp[i][1], ap, b0.y, accp[i][1]);
                    ffma2(accp[i][2], ap, b1.x, accp[i][2]);
                    ffma2(accp[i][3], ap, b1.y, accp[i][3]);
                }
            }
        }
#pragma unroll
        for (int i = 0; i < 4; ++i) {
            float* crow = g_gx + (rowbase + ty * 4 + i) * 512 + cb * 128;
            float2 v0 = unpack2(accp[i][0]), v1 = unpack2(accp[i][1]);
            float2 v2 = unpack2(accp[i][2]), v3 = unpack2(accp[i][3]);
            *(float4*)&crow[tx * 4]      = make_float4(v0.x, v0.y, v1.x, v1.y);
            *(float4*)&crow[64 + tx * 4] = make_float4(v2.x, v2.y, v3.x, v3.y);
        }
        // consumers of these gx rows run in a LATER kernel launch
    }
}

// ============================================================
// LSTM part B: t in [TSPLIT, TT), state from device globals
// ============================================================
__global__ void __launch_bounds__(512, 1)
lstm2_kernel(const float* __restrict__ whh,
             const float* __restrict__ bih, const float* __restrict__ bhh,
             float* __restrict__ out) {
    lstm_chain(blockIdx.x, TSPLIT, TT, g_hstate, g_cstate, whh, bih, bhh, out);
}

// ============================================================
// launch
// ============================================================
extern "C" void kernel_launch(void* const* d_in, const int* in_sizes, int n_in,
                              void* d_out, int out_size) {
    const int*   adj_idx = (const int*)  d_in[0];
    const float* adj_val = (const float*)d_in[1];
    const float* xs      = (const float*)d_in[2];
    const float* gw      = (const float*)d_in[3];
    const float* gb      = (const float*)d_in[4];
    const float* wih     = (const float*)d_in[5];
    const float* whh     = (const float*)d_in[6];
    const float* bih     = (const float*)d_in[7];
    const float* bhh     = (const float*)d_in[8];
    const float* h0      = (const float*)d_in[9];
    const float* c0      = (const float*)d_in[10];
    float* out = (float*)d_out;

    (void)in_sizes; (void)n_in; (void)out_size;

    const int GEMM_SMEM = 2 * 64 * 132 * 4;                       // 67584
    const int LSTM_SMEM = (1024 * 20 + 136 + 128 + 516) * 4;      // 85040

    static bool attr_done = false;
    if (!attr_done) {
        cudaFuncSetAttribute(support_kernel, cudaFuncAttributeMaxDynamicSharedMemorySize, GEMM_SMEM);
        cudaFuncSetAttribute(gatesxA_kernel, cudaFuncAttributeMaxDynamicSharedMemorySize, GEMM_SMEM);
        cudaFuncSetAttribute(combo_kernel,   cudaFuncAttributeMaxDynamicSharedMemorySize, LSTM_SMEM);
        cudaFuncSetAttribute(lstm2_kernel,   cudaFuncAttributeMaxDynamicSharedMemorySize, LSTM_SMEM);
        attr_done = true;
    }

    // init + CSR build (separate kernels — fusion is a proven anti-pattern here)
    init_kernel<<<192, 1024>>>();
    hist_kernel<<<NEDGE / 1024, 1024>>>(adj_idx);
    scan1_kernel<<<192, 1024>>>();
    scan2_kernel<<<1, 256>>>();
    scan3_kernel<<<192, 1024>>>();
    fill_kernel<<<NEDGE / 1024, 1024>>>(adj_idx, adj_val);

    // support GEMM
    support_kernel<<<1536, 256, GEMM_SMEM>>>(xs, gw);

    // gather
    gather_kernel<<<ROWS / 8, 256>>>();

    // gates_x for t < TSPLIT (rb < TSPLIT/2)
    gatesxA_kernel<<<dim3(TSPLIT / 2, 4), 256, GEMM_SMEM>>>(wih, gb);

    // overlap: LSTM[0,TSPLIT) on 64 CTAs || gates_x rb>=TSPLIT/2 on 84 CTAs
    combo_kernel<<<148, 512, LSTM_SMEM>>>(wih, gb, whh, bih, bhh, h0, c0, out);

    // LSTM [TSPLIT, TT)
    lstm2_kernel<<<64, 512, LSTM_SMEM>>>(whh, bih, bhh, out);
}

// round 16
// speedup vs baseline: 1.2466x; 1.0408x over previous
#include <cuda_runtime.h>
#include <cstdint>
#include <math.h>

#define S_T   12
#define NN    16384
#define EE    262144          // 2^18
#define D     128
#define BB    64
#define TT    3072            // S*N/B
#define ROWS  (S_T*NN)        // 196608
#define NEDGE (S_T*EE)        // 3,145,728
#define NRB   1536            // row-blocks of 128 rows (= 2 timesteps each)
#define TSPLIT 1216           // LSTM split point (timesteps)
#define ITEM_OFS (TSPLIT*2)   // first gatesx item handled inside combo
#define NITEMS_TOT (NRB*4)    // 6144

// ---- scratch (static device allocations; no runtime alloc allowed) ----
__device__ __align__(16) float g_support[(size_t)ROWS * D];
__device__ __align__(16) float g_acc[(size_t)ROWS * D];
__device__ __align__(16) float g_gx[(size_t)ROWS * 512];
__device__ int g_deg[ROWS];
__device__ int g_off[ROWS];
__device__ int g_cur[ROWS];
__device__ int g_bsum[256];
__device__ __align__(16) int2 g_epack[NEDGE];
__device__ int g_ticket;
__device__ __align__(16) float g_hstate[BB * 128];
__device__ __align__(16) float g_cstate[BB * 128];

// ---- packed f32x2 helpers ----
typedef unsigned long long u64;
__device__ __forceinline__ void ffma2(u64& d, u64 a, u64 b, u64 c) {
    asm("fma.rn.f32x2 %0, %1, %2, %3;" : "=l"(d) : "l"(a), "l"(b), "l"(c));
}
__device__ __forceinline__ u64 bcast2(float x) {
    u64 r;
    asm("mov.b64 %0, {%1, %1};" : "=l"(r) : "f"(x));
    return r;
}
__device__ __forceinline__ float2 unpack2(u64 v) {
    float2 r;
    asm("mov.b64 {%0, %1}, %2;" : "=f"(r.x), "=f"(r.y) : "l"(v));
    return r;
}
__device__ __forceinline__ float fsigm(float x) {
    return __fdividef(1.f, 1.f + __expf(-x));
}
__device__ __forceinline__ float ftanh(float x) {
    return __fdividef(2.f, 1.f + __expf(-2.f * x)) - 1.f;
}

// ---- cluster / mbarrier helpers (protocol proven in R12) ----
__device__ __forceinline__ uint32_t smem_u32(const void* p) {
    uint32_t a;
    asm("{ .reg .u64 t; cvta.to.shared.u64 t, %1; cvt.u32.u64 %0, t; }"
        : "=r"(a) : "l"(p));
    return a;
}
__device__ __forceinline__ uint32_t mapa_u32(uint32_t laddr, uint32_t rank) {
    uint32_t r;
    asm("mapa.shared::cluster.u32 %0, %1, %2;" : "=r"(r) : "r"(laddr), "r"(rank));
    return r;
}
__device__ __forceinline__ void mbar_init(uint32_t addr, uint32_t count) {
    asm volatile("mbarrier.init.shared.b64 [%0], %1;" :: "r"(addr), "r"(count) : "memory");
}
__device__ __forceinline__ void mbar_expect_tx(uint32_t addr, uint32_t bytes) {
    asm volatile("mbarrier.arrive.expect_tx.shared.b64 _, [%0], %1;"
                 :: "r"(addr), "r"(bytes) : "memory");
}
__device__ __forceinline__ void st_async_f32(uint32_t raddr, float v, uint32_t rmbar) {
    asm volatile("st.async.shared::cluster.mbarrier::complete_tx::bytes.b32 [%0], %1, [%2];"
                 :: "r"(raddr), "r"(__float_as_int(v)), "r"(rmbar) : "memory");
}
__device__ __forceinline__ void mbar_wait(uint32_t addr, int parity) {
    uint32_t done;
    asm volatile(
        "{\n\t.reg .pred p;\n\t"
        "mbarrier.try_wait.parity.acquire.cluster.shared::cta.b64 p, [%1], %2;\n\t"
        "selp.b32 %0, 1, 0, p;\n\t}"
        : "=r"(done) : "r"(addr), "r"((uint32_t)parity) : "memory");
    while (!done) {
        asm volatile(
            "{\n\t.reg .pred p;\n\t"
            "mbarrier.try_wait.parity.acquire.cluster.shared::cta.b64 p, [%1], %2, 0x989680;\n\t"
            "selp.b32 %0, 1, 0, p;\n\t}"
            : "=r"(done) : "r"(addr), "r"((uint32_t)parity) : "memory");
    }
}
#define CLUSTER_SYNC() do { \
    asm volatile("barrier.cluster.arrive.aligned;" ::: "memory"); \
    asm volatile("barrier.cluster.wait.aligned;" ::: "memory"); \
} while (0)

// ============================================================
// init: zero degree counters + ticket
// ============================================================
__global__ void init_kernel() {
    int gid = blockIdx.x * 1024 + threadIdx.x;
    g_deg[gid] = 0;
    if (gid == 0) g_ticket = 0;
}

// ============================================================
// CSR pipeline: histogram -> scan -> fill (packs src+val)
// ============================================================
__global__ void hist_kernel(const int* __restrict__ adj_idx) {
    int gid = blockIdx.x * 1024 + threadIdx.x;
    int s = gid >> 18, e = gid & (EE - 1);
    int dst = adj_idx[(size_t)s * 2 * EE + e];
    atomicAdd(&g_deg[s * NN + dst], 1);
}

__global__ void scan1_kernel() {                 // 192 blocks x 1024
    __shared__ int wsum[32];
    int tid = threadIdx.x, lane = tid & 31, warp = tid >> 5;
    int gid = blockIdx.x * 1024 + tid;
    int x = g_deg[gid];
    int v = x;
#pragma unroll
    for (int d = 1; d < 32; d <<= 1) {
        int t = __shfl_up_sync(0xffffffffu, v, d);
        if (lane >= d) v += t;
    }
    if (lane == 31) wsum[warp] = v;
    __syncthreads();
    if (warp == 0) {
        int w = wsum[lane];
#pragma unroll
        for (int d = 1; d < 32; d <<= 1) {
            int t = __shfl_up_sync(0xffffffffu, w, d);
            if (lane >= d) w += t;
        }
        wsum[lane] = w;
    }
    __syncthreads();
    int base = warp ? wsum[warp - 1] : 0;
    g_off[gid] = base + v - x;                   // exclusive
    if (tid == 1023) g_bsum[blockIdx.x] = base + v;
}

__global__ void scan2_kernel() {                 // 1 block x 256
    __shared__ int tmp[256];
    int tid = threadIdx.x;
    int x = (tid < 192) ? g_bsum[tid] : 0;
    tmp[tid] = x;
    __syncthreads();
#pragma unroll
    for (int d = 1; d < 256; d <<= 1) {
        int t = (tid >= d) ? tmp[tid - d] : 0;
        __syncthreads();
        tmp[tid] += t;
        __syncthreads();
    }
    if (tid < 192) g_bsum[tid] = tmp[tid] - x;   // exclusive
}

__global__ void scan3_kernel() {                 // 192 blocks x 1024
    int gid = blockIdx.x * 1024 + threadIdx.x;
    int v = g_off[gid] + g_bsum[blockIdx.x];
    g_off[gid] = v;
    g_cur[gid] = v;
}

__global__ void fill_kernel(const int* __restrict__ adj_idx,
                            const float* __restrict__ adj_val) {
    int gid = blockIdx.x * 1024 + threadIdx.x;
    int s = gid >> 18, e = gid & (EE - 1);
    const int* ib = adj_idx + (size_t)s * 2 * EE;
    int dst = ib[e];
    int src = ib[EE + e];
    float v  = adj_val[(size_t)s * EE + e];
    int pos = atomicAdd(&g_cur[s * NN + dst], 1);
    g_epack[pos] = make_int2(src, __float_as_int(v));
}

// ============================================================
// gather: acc[row] = sum_e val[e] * support[src[e]]
// ============================================================
__global__ void __launch_bounds__(256)
gather_kernel() {
    int wid  = blockIdx.x * 8 + (threadIdx.x >> 5);
    int lane = threadIdx.x & 31;
    int s = wid >> 14;

    int start = g_off[wid];
    int cnt   = g_deg[wid];

    const int2*  epk  = g_epack + start;
    const float* supp = g_support + (size_t)s * NN * D + lane * 4;

    float ax = 0.f, ay = 0.f, az = 0.f, aw = 0.f;
    int i = 0;
    for (; i + 4 <= cnt; i += 4) {
        int2 p0 = __ldg(&epk[i + 0]);
        int2 p1 = __ldg(&epk[i + 1]);
        int2 p2 = __ldg(&epk[i + 2]);
        int2 p3 = __ldg(&epk[i + 3]);
        float4 m0 = *(const float4*)(supp + (size_t)p0.x * D);
        float4 m1 = *(const float4*)(supp + (size_t)p1.x * D);
        float4 m2 = *(const float4*)(supp + (size_t)p2.x * D);
        float4 m3 = *(const float4*)(supp + (size_t)p3.x * D);
        float v0 = __int_as_float(p0.y), v1 = __int_as_float(p1.y);
        float v2 = __int_as_float(p2.y), v3 = __int_as_float(p3.y);
        ax += v0 * m0.x; ay += v0 * m0.y; az += v0 * m0.z; aw += v0 * m0.w;
        ax += v1 * m1.x; ay += v1 * m1.y; az += v1 * m1.z; aw += v1 * m1.w;
        ax += v2 * m2.x; ay += v2 * m2.y; az += v2 * m2.z; aw += v2 * m2.w;
        ax += v3 * m3.x; ay += v3 * m3.y; az += v3 * m3.z; aw += v3 * m3.w;
    }
    for (; i < cnt; ++i) {
        int2 p = __ldg(&epk[i]);
        float v = __int_as_float(p.y);
        float4 m = *(const float4*)(supp + (size_t)p.x * D);
        ax += v * m.x; ay += v * m.y; az += v * m.z; aw += v * m.w;
    }
    *(float4*)(g_acc + (size_t)wid * D + lane * 4) = make_float4(ax, ay, az, aw);
}

// ============================================================
// K1: support = xs @ gcn_weight (256 threads, 8x8 reg tile)
// ============================================================
__global__ void __launch_bounds__(256)
support_kernel(const float* __restrict__ X, const float* __restrict__ W) {
    extern __shared__ float sm[];
    float* As = sm;
    float* Bs = sm + 64 * 132;

    int tid = threadIdx.x;
    int tx = tid & 15, ty = tid >> 4;
    size_t rowbase = (size_t)blockIdx.x * 128;

    u64 accp[8][4];
#pragma unroll
    for (int i = 0; i < 8; ++i)
#pragma unroll
        for (int jj = 0; jj < 4; ++jj) accp[i][jj] = 0ull;

    for (int k0 = 0; k0 < 128; k0 += 64) {
        __syncthreads();
        for (int idx = tid; idx < 128 * 64; idx += 256) {
            int r = idx >> 6, k = idx & 63;
            As[k * 132 + r] = X[(rowbase + r) * 128 + k0 + k];
        }
        for (int idx = tid; idx < 64 * 128; idx += 256) {
            int k = idx >> 7, c = idx & 127;
            Bs[k * 132 + c] = W[(size_t)(k0 + k) * 128 + c];
        }
        __syncthreads();
#pragma unroll
        for (int k = 0; k < 64; ++k) {
            ulonglong2 b0 = *(const ulonglong2*)&Bs[k * 132 + tx * 4];
            ulonglong2 b1 = *(const ulonglong2*)&Bs[k * 132 + 64 + tx * 4];
            float4 a0 = *(const float4*)&As[k * 132 + ty * 4];
            float4 a1 = *(const float4*)&As[k * 132 + 64 + ty * 4];
            float af[8] = {a0.x,a0.y,a0.z,a0.w,a1.x,a1.y,a1.z,a1.w};
#pragma unroll
            for (int i = 0; i < 8; ++i) {
                u64 ap = bcast2(af[i]);
                ffma2(accp[i][0], ap, b0.x, accp[i][0]);
                ffma2(accp[i][1], ap, b0.y, accp[i][1]);
                ffma2(accp[i][2], ap, b1.x, accp[i][2]);
                ffma2(accp[i][3], ap, b1.y, accp[i][3]);
            }
        }
    }
#pragma unroll
    for (int i = 0; i < 8; ++i) {
        int r = (i < 4) ? (ty * 4 + i) : (64 + ty * 4 + i - 4);
        float* crow = g_support + (rowbase + r) * 128;
        float2 v0 = unpack2(accp[i][0]), v1 = unpack2(accp[i][1]);
        float2 v2 = unpack2(accp[i][2]), v3 = unpack2(accp[i][3]);
        *(float4*)&crow[tx * 4]      = make_float4(v0.x, v0.y, v1.x, v1.y);
        *(float4*)&crow[64 + tx * 4] = make_float4(v2.x, v2.y, v3.x, v3.y);
    }
}

// ============================================================
// gatesx part A: rb < TSPLIT/2
// ============================================================
__global__ void __launch_bounds__(256)
gatesxA_kernel(const float* __restrict__ wih, const float* __restrict__ gcn_bias) {
    extern __shared__ float sm[];
    float* As = sm;
    float* Bs = sm + 64 * 132;

    int tid = threadIdx.x;
    int tx = tid & 15, ty = tid >> 4;
    size_t rowbase = (size_t)blockIdx.x * 128;
    int cb = blockIdx.y;

    u64 accp[8][4];
#pragma unroll
    for (int i = 0; i < 8; ++i)
#pragma unroll
        for (int jj = 0; jj < 4; ++jj) accp[i][jj] = 0ull;

    for (int k0 = 0; k0 < 128; k0 += 64) {
        __syncthreads();
        for (int idx = tid; idx < 128 * 64; idx += 256) {
            int r = idx >> 6, k = idx & 63;
            float x = g_acc[(rowbase + r) * 128 + k0 + k] + __ldg(&gcn_bias[k0 + k]);
            As[k * 132 + r] = fmaxf(x, 0.f);
        }
        for (int idx = tid; idx < 128 * 64; idx += 256) {
            int c = idx >> 6, k = idx & 63;
            Bs[k * 132 + c] = wih[((size_t)(cb * 128 + c)) * 128 + k0 + k];
        }
        __syncthreads();
#pragma unroll
        for (int k = 0; k < 64; ++k) {
            ulonglong2 b0 = *(const ulonglong2*)&Bs[k * 132 + tx * 4];
            ulonglong2 b1 = *(const ulonglong2*)&Bs[k * 132 + 64 + tx * 4];
            float4 a0 = *(const float4*)&As[k * 132 + ty * 4];
            float4 a1 = *(const float4*)&As[k * 132 + 64 + ty * 4];
            float af[8] = {a0.x,a0.y,a0.z,a0.w,a1.x,a1.y,a1.z,a1.w};
#pragma unroll
            for (int i = 0; i < 8; ++i) {
                u64 ap = bcast2(af[i]);
                ffma2(accp[i][0], ap, b0.x, accp[i][0]);
                ffma2(accp[i][1], ap, b0.y, accp[i][1]);
                ffma2(accp[i][2], ap, b1.x, accp[i][2]);
                ffma2(accp[i][3], ap, b1.y, accp[i][3]);
            }
        }
    }
#pragma unroll
    for (int i = 0; i < 8; ++i) {
        int r = (i < 4) ? (ty * 4 + i) : (64 + ty * 4 + i - 4);
        float* crow = g_gx + (rowbase + r) * 512 + cb * 128;
        float2 v0 = unpack2(accp[i][0]), v1 = unpack2(accp[i][1]);
        float2 v2 = unpack2(accp[i][2]), v3 = unpack2(accp[i][3]);
        *(float4*)&crow[tx * 4]      = make_float4(v0.x, v0.y, v1.x, v1.y);
        *(float4*)&crow[64 + tx * 4] = make_float4(v2.x, v2.y, v3.x, v3.y);
    }
}

// ============================================================
// LSTM chain (single-CTA, R13 config): one CTA per batch lane.
// ============================================================
__device__ __forceinline__ void lstm_chain(
    int b, int t0, int t1,
    const float* __restrict__ hin, const float* __restrict__ cin,
    const float* __restrict__ whh, const float* __restrict__ bih,
    const float* __restrict__ bhh, float* __restrict__ out)
{
    extern __shared__ float sm[];
    float* sWs = sm;                  // [1024 slices][16] stride 20, slice = o*2+pos
    float* sH  = sm + 1024 * 20;      // [136]: half h at pos*68
    float* sC  = sH + 136;            // [128]
    float* sG  = sC + 128;            // [516]

    int t = threadIdx.x;
    int p = t >> 1, pos = t & 1;
    int oa = p, ob = p + 256;
    int kb = pos * 64;
    int ofin = pos ? ob : oa;

    for (int idx = t; idx < 1024 * 16; idx += 512) {
        int slice = idx >> 4, kk = idx & 15;
        int o = slice >> 1, ps = slice & 1;
        sWs[slice * 20 + kk] = whh[(size_t)o * 128 + ps * 64 + kk];
    }
    u64 wra[24], wrb[24];
#pragma unroll
    for (int m = 0; m < 24; ++m) {
        wra[m] = *(const u64*)&whh[(size_t)oa * 128 + kb + 16 + 2 * m];
        wrb[m] = *(const u64*)&whh[(size_t)ob * 128 + kb + 16 + 2 * m];
    }

    if (t < 128) {
        sH[(t >> 6) * 68 + (t & 63)] = hin[b * 128 + t];
        sC[t] = cin[b * 128 + t];
    }
    float bias = bih[ofin] + bhh[ofin];
    int gate = ofin >> 7;
    float nsc = (gate == 2) ? 2.f : 1.f;
    float nof = (gate == 2) ? -1.f : 0.f;
    const float* gxp = g_gx + (size_t)b * 512 + ofin;
    float gxc = gxp[(size_t)t0 * 32768];
    __syncthreads();

    const float* wap = &sWs[(size_t)(oa * 2 + pos) * 20];
    const float* wbp = &sWs[(size_t)(ob * 2 + pos) * 20];
    const float* hp  = &sH[pos * 68];
    int sgi = ofin + ((ofin >> 8) << 2);

    for (int tt = t0; tt < t1; ++tt) {
        float gxn = (tt + 1 < t1) ? gxp[(size_t)(tt + 1) * 32768] : 0.f;

        u64 a0 = 0ull, a1 = 0ull, b0 = 0ull, b1 = 0ull;
#pragma unroll
        for (int kk = 0; kk < 16; kk += 4) {
            ulonglong2 hv = *(const ulonglong2*)&hp[kk];
            ulonglong2 wa = *(const ulonglong2*)&wap[kk];
            ulonglong2 wb = *(const ulonglong2*)&wbp[kk];
            ffma2(a0, hv.x, wa.x, a0);  ffma2(a1, hv.y, wa.y, a1);
            ffma2(b0, hv.x, wb.x, b0);  ffma2(b1, hv.y, wb.y, b1);
        }
#pragma unroll
        for (int kk = 0; kk < 48; kk += 4) {
            ulonglong2 hv = *(const ulonglong2*)&hp[16 + kk];
            ffma2(a0, hv.x, wra[kk / 2], a0);  ffma2(a1, hv.y, wra[kk / 2 + 1], a1);
            ffma2(b0, hv.x, wrb[kk / 2], b0);  ffma2(b1, hv.y, wrb[kk / 2 + 1], b1);
        }
        float2 qa0 = unpack2(a0), qa1 = unpack2(a1);
        float2 qb0 = unpack2(b0), qb1 = unpack2(b1);
        float pa = (qa0.x + qa0.y) + (qa1.x + qa1.y);
        float pb = (qb0.x + qb0.y) + (qb1.x + qb1.y);
        float xa = pa + __shfl_xor_sync(0xffffffffu, pa, 1);
        float xb = pb + __shfl_xor_sync(0xffffffffu, pb, 1);
        float pre = (pos ? xb : xa) + gxc + bias;
        sG[sgi] = nsc * fsigm(nsc * pre) + nof;
        __syncthreads();

        if (t < 128) {
            float i_ = sG[t],        f_ = sG[128 + t];
            float g_ = sG[260 + t],  o_ = sG[388 + t];
            float c = f_ * sC[t] + i_ * g_;
            sC[t] = c;
            float h = o_ * ftanh(c);
            sH[(t >> 6) * 68 + (t & 63)] = h;
            out[((size_t)tt * 64 + b) * 128 + t] = h;
        }
        __syncthreads();
        gxc = gxn;
    }

    if (t < 128) {
        g_hstate[b * 128 + t] = sH[(t >> 6) * 68 + (t & 63)];
        g_cstate[b * 128 + t] = sC[t];
    }
}

// ============================================================
// COMBO kernel: 148 CTAs x 512 threads, NO cross-CTA comms.
//  CTA 0..63   : single-CTA LSTM for t in [0, TSPLIT)
//  CTA 64..147 : gates_x producer for items [ITEM_OFS, NITEMS_TOT)
// ============================================================
__global__ void __launch_bounds__(512, 1)
combo_kernel(const float* __restrict__ wih,  const float* __restrict__ gb,
             const float* __restrict__ whh,
             const float* __restrict__ bih,  const float* __restrict__ bhh,
             const float* __restrict__ h0,   const float* __restrict__ c0,
             float* __restrict__ out) {
    if (blockIdx.x < 64) {
        lstm_chain(blockIdx.x, 0, TSPLIT, h0, c0, whh, bih, bhh, out);
        return;
    }

    extern __shared__ float sm[];
    float* As = sm;
    float* Bs = sm + 64 * 132;
    __shared__ int sItem;
    int tid = threadIdx.x;
    int tx = tid & 15, ty = tid >> 4;

    for (;;) {
        if (tid == 0) sItem = ITEM_OFS + atomicAdd(&g_ticket, 1);
        __syncthreads();
        int item = sItem;
        if (item >= NITEMS_TOT) break;
        int rb = item >> 2, cb = item & 3;
        size_t rowbase = (size_t)rb * 128;

        u64 accp[4][4];
#pragma unroll
        for (int i = 0; i < 4; ++i)
#pragma unroll
            for (int jj = 0; jj < 4; ++jj) accp[i][jj] = 0ull;

        for (int k0 = 0; k0 < 128; k0 += 64) {
            __syncthreads();
            for (int idx = tid; idx < 128 * 64; idx += 512) {
                int r = idx >> 6, k = idx & 63;
                float x = g_acc[(rowbase + r) * 128 + k0 + k] + __ldg(&gb[k0 + k]);
                As[k * 132 + r] = fmaxf(x, 0.f);
            }
            for (int idx = tid; idx < 128 * 64; idx += 512) {
                int c = idx >> 6, k = idx & 63;
                Bs[k * 132 + c] = wih[((size_t)(cb * 128 + c)) * 128 + k0 + k];
            }
            __syncthreads();
#pragma unroll
            for (int k = 0; k < 64; ++k) {
                ulonglong2 b0 = *(const ulonglong2*)&Bs[k * 132 + tx * 4];
                ulonglong2 b1 = *(const ulonglong2*)&Bs[k * 132 + 64 + tx * 4];
                float4 a = *(const float4*)&As[k * 132 + ty * 4];
                float af[4] = {a.x, a.y, a.z, a.w};
#pragma unroll
                for (int i = 0; i < 4; ++i) {
                    u64 ap = bcast2(af[i]);
                    ffma2(accp[i][0], ap, b0.x, accp[i][0]);
                    ffma2(accp[i][1], ap, b0.y, accp[i][1]);
                    ffma2(accp[i][2], ap, b1.x, accp[i][2]);
                    ffma2(accp[i][3], ap, b1.y, accp[i][3]);
                }
            }
        }
#pragma unroll
        for (int i = 0; i < 4; ++i) {
            float* crow = g_gx + (rowbase + ty * 4 + i) * 512 + cb * 128;
            float2 v0 = unpack2(accp[i][0]), v1 = unpack2(accp[i][1]);
            float2 v2 = unpack2(accp[i][2]), v3 = unpack2(accp[i][3]);
            *(float4*)&crow[tx * 4]      = make_float4(v0.x, v0.y, v1.x, v1.y);
            *(float4*)&crow[64 + tx * 4] = make_float4(v2.x, v2.y, v3.x, v3.y);
        }
    }
}

// ============================================================
// LSTM part B: 2-CTA cluster per batch lane, t in [TSPLIT, TT).
// Rank r owns j in [64r, 64r+64) of all 4 gates (256 outputs).
// Thread (idx, half): output o over k in [64*half, 64*half+64),
// ALL 64 weights in 32 u64 registers (zero weight LDS).
// KEY REORDER vs R12: only remote-half warps (half != r) wait
// on the mbarrier; local-half warps start their dot immediately,
// hiding the ~300cyc DSMEM transit behind local compute.
// Protocol (double-buffered sH + 2 mbarriers, st.async 64
// floats/step each way, expect_tx 256B) is R12-proven.
// ============================================================
__global__ void __launch_bounds__(512, 1) __cluster_dims__(2, 1, 1)
lstm2_kernel(const float* __restrict__ whh,
             const float* __restrict__ bih, const float* __restrict__ bhh,
             float* __restrict__ out) {
    __shared__ __align__(16) float sHbuf[2][128];
    __shared__ float sC[64];
    __shared__ __align__(16) float sP[512];
    __shared__ __align__(8) unsigned long long sMbar[2];

    int b = blockIdx.x >> 1;
    int r = blockIdx.x & 1;
    int tid  = threadIdx.x;               // 0..511
    int half = tid >> 8;                  // warp-uniform (warps 0-7: half0, 8-15: half1)
    int idx  = tid & 255;
    int g    = idx >> 6, u = idx & 63;
    int o    = g * 128 + 64 * r + u;      // output column in [0,512)
    int kb   = half * 64;
    bool waiter = (half != r);            // this half's h slice is remote

    u64 wreg[32];
#pragma unroll
    for (int m = 0; m < 32; ++m)
        wreg[m] = *(const u64*)&whh[(size_t)o * 128 + kb + 2 * m];

    uint32_t mbar[2] = { smem_u32(&sMbar[0]), smem_u32(&sMbar[1]) };
    uint32_t peer = (uint32_t)(r ^ 1);
    uint32_t p_mbar[2] = { mapa_u32(mbar[0], peer), mapa_u32(mbar[1], peer) };

    if (tid == 0) { mbar_init(mbar[0], 1); mbar_init(mbar[1], 1); }

    if (tid < 128) sHbuf[0][tid] = g_hstate[b * 128 + tid];
    if (tid < 64)  sC[tid] = g_cstate[b * 128 + 64 * r + tid];

    int j = 64 * r + (tid & 63);
    uint32_t raddr[2] = { mapa_u32(smem_u32(&sHbuf[0][j]), peer),
                          mapa_u32(smem_u32(&sHbuf[1][j]), peer) };

    float bias = bih[o] + bhh[o];
    const float* gxp = g_gx + (size_t)b * 512 + o;
    float gxc = (half == 0) ? gxp[(size_t)TSPLIT * 32768] : 0.f;

    __syncthreads();
    CLUSTER_SYNC();   // peer's mbarrier init + sH fill complete

    int par0 = 0, par1 = 0;
    const int N = TT - TSPLIT;

    for (int n = 0; n < N; ++n) {
        int t = TSPLIT + n;
        float gxn = 0.f;
        if (half == 0 && n + 1 < N) gxn = gxp[(size_t)(t + 1) * 32768];

        // only remote-half warps block on the peer's h for step n-1;
        // local-half warps proceed straight into their dot.
        if (n > 0) {
            int m = (n - 1) & 1;
            if (m == 0) { if (waiter) mbar_wait(mbar[0], par0); par0 ^= 1; }
            else        { if (waiter) mbar_wait(mbar[1], par1); par1 ^= 1; }
        }
        const float* hcur = sHbuf[n & 1];

        u64 a0 = 0ull, a1 = 0ull;
#pragma unroll
        for (int kk = 0; kk < 64; kk += 4) {
            ulonglong2 hv = *(const ulonglong2*)&hcur[kb + kk];
            ffma2(a0, hv.x, wreg[kk / 2],     a0);
            ffma2(a1, hv.y, wreg[kk / 2 + 1], a1);
        }
        float2 qa = unpack2(a0), qb = unpack2(a1);
        float p = (qa.x + qa.y) + (qb.x + qb.y);
        if (half == 0) p += gxc + bias;
        sP[half * 256 + idx] = p;
        __syncthreads();

        if (tid < 64) {
            float i_ = fsigm(sP[tid]       + sP[256 + tid]);
            float f_ = fsigm(sP[64 + tid]  + sP[320 + tid]);
            float g_ = ftanh(sP[128 + tid] + sP[384 + tid]);
            float o_ = fsigm(sP[192 + tid] + sP[448 + tid]);
            float c = f_ * sC[tid] + i_ * g_;
            sC[tid] = c;
            float h = o_ * ftanh(c);
            int nb = (n + 1) & 1;
            sHbuf[nb][j] = h;                          // local slice
            st_async_f32(raddr[nb], h, p_mbar[n & 1]); // remote + signal
            out[((size_t)t * 64 + b) * 128 + j] = h;
        }
        if (tid == 0) mbar_expect_tx(mbar[n & 1], 256);
        __syncthreads();
        gxc = gxn;
    }

    // drain final incoming exchange before smem goes away
    {
        int m = (N - 1) & 1;
        if (m == 0) mbar_wait(mbar[0], par0);
        else        mbar_wait(mbar[1], par1);
    }
    if (tid < 64) {
        g_hstate[b * 128 + j] = sHbuf[N & 1][j];
        g_cstate[b * 128 + j] = sC[tid];
    }
    CLUSTER_SYNC();
}

// ============================================================
// launch
// ============================================================
extern "C" void kernel_launch(void* const* d_in, const int* in_sizes, int n_in,
                              void* d_out, int out_size) {
    const int*   adj_idx = (const int*)  d_in[0];
    const float* adj_val = (const float*)d_in[1];
    const float* xs      = (const float*)d_in[2];
    const float* gw      = (const float*)d_in[3];
    const float* gb      = (const float*)d_in[4];
    const float* wih     = (const float*)d_in[5];
    const float* whh     = (const float*)d_in[6];
    const float* bih     = (const float*)d_in[7];
    const float* bhh     = (const float*)d_in[8];
    const float* h0      = (const float*)d_in[9];
    const float* c0      = (const float*)d_in[10];
    float* out = (float*)d_out;

    (void)in_sizes; (void)n_in; (void)out_size;

    const int GEMM_SMEM = 2 * 64 * 132 * 4;                       // 67584
    const int LSTM_SMEM = (1024 * 20 + 136 + 128 + 516) * 4;      // 85040

    static bool attr_done = false;
    if (!attr_done) {
        cudaFuncSetAttribute(support_kernel, cudaFuncAttributeMaxDynamicSharedMemorySize, GEMM_SMEM);
        cudaFuncSetAttribute(gatesxA_kernel, cudaFuncAttributeMaxDynamicSharedMemorySize, GEMM_SMEM);
        cudaFuncSetAttribute(combo_kernel,   cudaFuncAttributeMaxDynamicSharedMemorySize, LSTM_SMEM);
        attr_done = true;
    }

    // init + CSR build
    init_kernel<<<192, 1024>>>();
    hist_kernel<<<NEDGE / 1024, 1024>>>(adj_idx);
    scan1_kernel<<<192, 1024>>>();
    scan2_kernel<<<1, 256>>>();
    scan3_kernel<<<192, 1024>>>();
    fill_kernel<<<NEDGE / 1024, 1024>>>(adj_idx, adj_val);

    // support GEMM
    support_kernel<<<1536, 256, GEMM_SMEM>>>(xs, gw);

    // gather
    gather_kernel<<<ROWS / 8, 256>>>();

    // gates_x for t < TSPLIT
    gatesxA_kernel<<<dim3(TSPLIT / 2, 4), 256, GEMM_SMEM>>>(wih, gb);

    // overlap: single-CTA LSTM[0,TSPLIT) on 64 CTAs || gates_x on 84 CTAs
    combo_kernel<<<148, 512, LSTM_SMEM>>>(wih, gb, whh, bih, bhh, h0, c0, out);

    // LSTM [TSPLIT, TT): 2-CTA cluster per lane, latency-hiding reorder
    lstm2_kernel<<<128, 512>>>(whh, bih, bhh, out);
}